// round 16
// baseline (speedup 1.0000x reference)
#include <cuda_runtime.h>
#include <cuda_bf16.h>
#include <cstdint>

// Problem constants
#define AP 48        // paths
#define LL 64        // length
#define DD 64        // channels
#define MM 63        // L-1 (increments)
#define PER_GRAM (AP*AP)          // 2304

#define NPB 96                    // 48 X blocks + 48 Y blocks (64 padded rows)
#define ROWS (NPB*64)             // 6144
#define NTILE 48                  // tiles per dim (128 rows each)
#define NTRI (NTILE*(NTILE+1)/2)  // 1176 upper-triangle tiles
#define NHT (NTRI*2)              // 2352 half-tiles (128 x 64)
#define NK2 (NTRI*4)              // 4704 (tile, sub) result slots

// Static scratch. g_Ks zero-init; inactive diagonal sub-slots stay 0.
__device__ __nv_bfloat16 g_dZhi[(size_t)ROWS * 64];   // split increments (hi)
__device__ __nv_bfloat16 g_dZlo[(size_t)ROWS * 64];   // split increments (lo)
__device__ float g_Ks[NK2];
__device__ unsigned g_ctr;

// smem (u32 units), row stride 36 u32 (72 bf16) -> conflict-free frag LDS:
//   sAhi [128][36] @0      sAlo [128][36] @4608
//   sBhi [ 64][36] @9216   sBlo [ 64][36] @11520   total 13824 u32 = 55296 B
// pde phase: sT = 2 sub-blocks [64][66] floats, aliases A region (33.8KB)
#define ASTRW 36
#define OFF_ALO 4608
#define OFF_BHI 9216
#define OFF_BLO 11520
#define TSTR 66
#define SUB_FLOATS (64*TSTR)
#define DYN_BYTES 55296

// ---------------------------------------------------------------------------
// Kernel 0: split-bf16 padded increments + counter reset.
// ---------------------------------------------------------------------------
__global__ void __launch_bounds__(256) dz_kernel(
    const float* __restrict__ X, const float* __restrict__ Y)
{
    const int gi = blockIdx.x * 256 + threadIdx.x;    // 98304 = 6144*16
    if (gi == 0) g_ctr = 0u;

    const int row = gi >> 4;
    const int d4  = gi & 15;
    const int blk = row >> 6;
    const int i   = row & 63;

    float4 v = make_float4(0.f, 0.f, 0.f, 0.f);
    if (i < MM) {
        const float* src = (blk < AP) ? (X + blk * (LL * DD))
                                      : (Y + (blk - AP) * (LL * DD));
        const float4 hi = *reinterpret_cast<const float4*>(src + (i + 1) * DD + 4 * d4);
        const float4 lo = *reinterpret_cast<const float4*>(src + i * DD + 4 * d4);
        v = make_float4(hi.x - lo.x, hi.y - lo.y, hi.z - lo.z, hi.w - lo.w);
    }

    __nv_bfloat16 h[4], l[4];
    const float vv[4] = {v.x, v.y, v.z, v.w};
#pragma unroll
    for (int c = 0; c < 4; c++) {
        h[c] = __float2bfloat16(vv[c]);
        l[c] = __float2bfloat16(vv[c] - __bfloat162float(h[c]));
    }
    __nv_bfloat162* dh = reinterpret_cast<__nv_bfloat162*>(g_dZhi) + row * 32 + 2 * d4;
    __nv_bfloat162* dl = reinterpret_cast<__nv_bfloat162*>(g_dZlo) + row * 32 + 2 * d4;
    dh[0] = __nv_bfloat162(h[0], h[1]);
    dh[1] = __nv_bfloat162(h[2], h[3]);
    dl[0] = __nv_bfloat162(l[0], l[1]);
    dl[1] = __nv_bfloat162(l[2], l[3]);
}

// ---------------------------------------------------------------------------
// Fused kernel: per 128x64 half-tile (tile u>=t, col half hh):
//   phase 1: split-bf16 mma.sync SYRK (8 warps x 16 rows x 64 cols, 32 accs)
//   phase 2: epilogue to 2 smem sub-blocks [64][66]
//   phase 3: warps 0-1 run wavefront Goursat PDE
//   phase 4: last CTA reduces
// ---------------------------------------------------------------------------
__global__ void __launch_bounds__(256, 3) sig_kernel(
    const float* __restrict__ X, const float* __restrict__ Y,
    float* __restrict__ out)
{
    extern __shared__ uint32_t smw[];
    uint32_t* sAhi = smw;
    uint32_t* sAlo = smw + OFF_ALO;
    uint32_t* sBhi = smw + OFF_BHI;
    uint32_t* sBlo = smw + OFF_BLO;
    float*    sT   = reinterpret_cast<float*>(smw);   // pde phase alias

    const int tid  = threadIdx.x;
    const int lane = tid & 31;
    const int wid  = tid >> 5;
    const int gid  = lane >> 2;     // 0..7
    const int tig  = lane & 3;      // 0..3

    const int tile = blockIdx.x >> 1;
    const int hh   = blockIdx.x & 1;
    int q = tile, t = 0;
    while (q >= NTILE - t) { q -= NTILE - t; t++; }
    const int u = t + q;
    const int gr0 = t * 128;
    const int gc0 = u * 128 + hh * 64;

    // ---- phase 0: vectorized tile loads (uint4, coalesced) ----------------
    {
        const uint4* gh = reinterpret_cast<const uint4*>(g_dZhi);  // 8 uint4/row
        const uint4* gl = reinterpret_cast<const uint4*>(g_dZlo);
        // A: 128 rows x 8 uint4 x {hi,lo} = 2048 uint4
        for (int idx = tid; idx < 1024; idx += 256) {
            const int m = idx >> 3;
            const int qq = idx & 7;
            const int src = (gr0 + m) * 8 + qq;
            reinterpret_cast<uint4*>(sAhi)[m * 9 + qq] = gh[src];
            reinterpret_cast<uint4*>(sAlo)[m * 9 + qq] = gl[src];
        }
        // B: 64 rows x 8 uint4 x {hi,lo}
        for (int idx = tid; idx < 512; idx += 256) {
            const int m = idx >> 3;
            const int qq = idx & 7;
            const int src = (gc0 + m) * 8 + qq;
            reinterpret_cast<uint4*>(sBhi)[m * 9 + qq] = gh[src];
            reinterpret_cast<uint4*>(sBlo)[m * 9 + qq] = gl[src];
        }
    }
    __syncthreads();

    // ---- phase 1: mma.sync mainloop (warp: rows 16*wid..+15, 64 cols) -----
    const int mb = wid * 16;
    float c[8][4];
#pragma unroll
    for (int j = 0; j < 8; j++)
#pragma unroll
        for (int e = 0; e < 4; e++) c[j][e] = 0.0f;

#pragma unroll
    for (int ks = 0; ks < 4; ks++) {
        const int kc0 = 8 * ks + tig;
        const int kc1 = kc0 + 4;
        const int ar0 = (mb + gid) * ASTRW;
        const int ar1 = (mb + gid + 8) * ASTRW;

        const uint32_t ah0 = sAhi[ar0 + kc0], ah1 = sAhi[ar1 + kc0];
        const uint32_t ah2 = sAhi[ar0 + kc1], ah3 = sAhi[ar1 + kc1];
        const uint32_t al0 = sAlo[ar0 + kc0], al1 = sAlo[ar1 + kc0];
        const uint32_t al2 = sAlo[ar0 + kc1], al3 = sAlo[ar1 + kc1];

#pragma unroll
        for (int j = 0; j < 8; j++) {
            const int br = (8 * j + gid) * ASTRW;
            const uint32_t bh0 = sBhi[br + kc0], bh1 = sBhi[br + kc1];
            const uint32_t bl0 = sBlo[br + kc0], bl1 = sBlo[br + kc1];

            asm volatile(
                "mma.sync.aligned.m16n8k16.row.col.f32.bf16.bf16.f32 "
                "{%0,%1,%2,%3}, {%4,%5,%6,%7}, {%8,%9}, {%0,%1,%2,%3};"
                : "+f"(c[j][0]), "+f"(c[j][1]), "+f"(c[j][2]), "+f"(c[j][3])
                : "r"(ah0), "r"(ah1), "r"(ah2), "r"(ah3), "r"(bh0), "r"(bh1));
            asm volatile(
                "mma.sync.aligned.m16n8k16.row.col.f32.bf16.bf16.f32 "
                "{%0,%1,%2,%3}, {%4,%5,%6,%7}, {%8,%9}, {%0,%1,%2,%3};"
                : "+f"(c[j][0]), "+f"(c[j][1]), "+f"(c[j][2]), "+f"(c[j][3])
                : "r"(ah0), "r"(ah1), "r"(ah2), "r"(ah3), "r"(bl0), "r"(bl1));
            asm volatile(
                "mma.sync.aligned.m16n8k16.row.col.f32.bf16.bf16.f32 "
                "{%0,%1,%2,%3}, {%4,%5,%6,%7}, {%8,%9}, {%0,%1,%2,%3};"
                : "+f"(c[j][0]), "+f"(c[j][1]), "+f"(c[j][2]), "+f"(c[j][3])
                : "r"(al0), "r"(al1), "r"(al2), "r"(al3), "r"(bh0), "r"(bh1));
        }
    }
    __syncthreads();   // done reading A/B smem

    // ---- phase 2: epilogue to sT sub-blocks [64][TSTR] --------------------
    {
        const int r   = wid >> 2;            // sub-row (0/1)
        const int lr0 = (mb & 63) + gid;
        const int lr1 = lr0 + 8;
#pragma unroll
        for (int j = 0; j < 8; j++) {
            const int col = 8 * j + 2 * tig;
            float* d0 = sT + r * SUB_FLOATS + lr0 * TSTR + col;
            float* d1 = sT + r * SUB_FLOATS + lr1 * TSTR + col;
            *reinterpret_cast<float2*>(d0) = make_float2(c[j][0], c[j][1]);
            *reinterpret_cast<float2*>(d1) = make_float2(c[j][2], c[j][3]);
        }
    }
    __syncthreads();

    // ---- phase 3: wavefront Goursat PDE, warps 0-1 ------------------------
    // K[r][c] = K[r][c-1] + K[r-1][c] + K[r-1][c-1]*(inc[r-1][c-1]-1).
    // Lane l owns cols c0=2l, c1=2l+1; 2-row block b at step s = l + b.
    if (wid < 2) {
        const int pa = 2 * t + wid;
        const int pb = 2 * u + hh;
        if (pa <= pb) {
            float w;
            if (pa < AP && pb >= AP) w = -2.0f / (float)PER_GRAM;       // XY
            else w = ((pa == pb) ? 1.0f : 2.0f) / (float)PER_GRAM;      // XX/YY

            const float* base = sT + wid * SUB_FLOATS;
            const int c0  = 2 * lane;
            const int cm1 = (c0 == 0) ? 0 : (c0 - 1);
            const bool lane0 = (lane == 0);

            float t0 = 1.0f, t1 = 1.0f;
            float y0 = 1.0f;
            float nt1_prev = 1.0f;            // = shfl(z) feed (z-reuse trick)

#pragma unroll 1
            for (int s = 0; s < 63; s++) {
                const float ny0 = __shfl_up_sync(0xffffffffu, y0, 1);
                const float nt1 = __shfl_up_sync(0xffffffffu, t1, 1);
                const float nz  = nt1_prev;   // == shfl of pre-prev t1
                nt1_prev = nt1;

                const int b = s - lane;
                const bool act  = (b >= 0) & (b <= 31);
                const bool row2 = (b >= 0) & (b <= 30);

                if (act) {
                    const int r0 = 2 * b + 1;
                    const float* rp = base + (r0 - 1) * TSTR;
                    const float i00 = rp[cm1];
                    const float i01 = rp[c0];
                    const float i10 = rp[TSTR + cm1];
                    const float i11 = rp[TSTR + c0];

                    const float A = lane0 ? 1.0f : fmaf(nz, i00 - 1.0f, ny0 + t0);
                    const float B = fmaf(t0, i01 - 1.0f, A + t1);

                    if (row2) {
                        const float C = lane0 ? 1.0f : fmaf(ny0, i10 - 1.0f, nt1 + A);
                        const float D = fmaf(A, i11 - 1.0f, C + B);
                        t0 = C; t1 = D;
                    } else {
                        t0 = A; t1 = B;
                    }
                    y0 = B;
                }
            }

            if (lane == 31) {
                g_Ks[tile * 4 + wid * 2 + hh] = w * y0;   // K[63][63], weighted
                __threadfence();                           // writer-side fence
            }
        }
    }

    // ---- phase 4: last CTA reduces ----------------------------------------
    __syncthreads();
    __shared__ bool s_is_last;
    if (tid == 0)
        s_is_last = (atomicAdd(&g_ctr, 1u) == (unsigned)(gridDim.x - 1));
    __syncthreads();
    if (!s_is_last) return;

    __shared__ float sdata[256];
    float s = 0.0f;
    for (int p = tid; p < NK2; p += 256) s += __ldcg(&g_Ks[p]);

    float s2 = 0.0f;
    for (int idx = tid; idx < AP * DD; idx += 256) {
        const int aa = idx >> 6;
        const int d  = idx & 63;
        const float diff = X[aa * (LL * DD) + d] - Y[aa * (LL * DD) + d];
        s2 = fmaf(diff, diff, s2);
    }
    s += s2 * (1.0f / (float)(AP * DD));

    sdata[tid] = s;
    __syncthreads();
    for (int k = 128; k > 0; k >>= 1) {
        if (tid < k) sdata[tid] += sdata[tid + k];
        __syncthreads();
    }
    if (tid == 0) out[0] = sdata[0];
}

// ---------------------------------------------------------------------------
extern "C" void kernel_launch(void* const* d_in, const int* in_sizes, int n_in,
                              void* d_out, int out_size)
{
    const float* X = (const float*)d_in[0];
    const float* Y = (const float*)d_in[1];
    float* out = (float*)d_out;

    static bool attr_done = false;
    if (!attr_done) {
        cudaFuncSetAttribute(sig_kernel,
                             cudaFuncAttributeMaxDynamicSharedMemorySize,
                             DYN_BYTES);
        attr_done = true;
    }

    dz_kernel<<<384, 256>>>(X, Y);
    sig_kernel<<<NHT, 256, DYN_BYTES>>>(X, Y, out);
}

// round 17
// speedup vs baseline: 1.2053x; 1.2053x over previous
#include <cuda_runtime.h>
#include <cuda_bf16.h>
#include <cstdint>

// Problem constants
#define AP 48        // paths
#define LL 64        // length
#define DD 64        // channels
#define MM 63        // L-1 (increments)
#define PER_GRAM (AP*AP)          // 2304

#define NPB 96                    // 48 X blocks + 48 Y blocks (64 padded rows)
#define ROWS (NPB*64)             // 6144
#define NTILE 48                  // tiles per dim (128 rows each)
#define NTRI (NTILE*(NTILE+1)/2)  // 1176 upper-triangle tiles
#define NK2 (NTRI*4)              // 4704 (tile, sub) result slots

// Static scratch. g_Ks zero-init; inactive diagonal sub-slots stay 0.
__device__ __nv_bfloat16 g_dZhi[(size_t)ROWS * 64];   // split increments (hi)
__device__ __nv_bfloat16 g_dZlo[(size_t)ROWS * 64];   // split increments (lo)
__device__ float g_Ks[NK2];
__device__ unsigned g_ctr;

// smem: mma phase  4 tiles [128 rows][36 b32] (72 bf16/row = 144 B stride)
//       pde phase  sT = 4 sub-blocks [64][66] floats (aliases)
#define ASTRW 36                       // b32 per row
#define ROW_BYTES 144
#define TILE_U32 (128*ASTRW)           // 4608
#define TSTR 66
#define SUB_FLOATS (64*TSTR)
#define DYN_BYTES (4*TILE_U32*4)       // 73728 B

__device__ __forceinline__ uint32_t smem_u32(const void* p) {
    uint32_t a;
    asm("{ .reg .u64 t; cvta.to.shared.u64 t, %1; cvt.u32.u64 %0, t; }"
        : "=r"(a) : "l"(p));
    return a;
}

__device__ __forceinline__ void ldm_x4(uint32_t& r0, uint32_t& r1,
                                       uint32_t& r2, uint32_t& r3,
                                       uint32_t addr) {
    asm volatile("ldmatrix.sync.aligned.m8n8.x4.shared.b16 {%0,%1,%2,%3}, [%4];"
                 : "=r"(r0), "=r"(r1), "=r"(r2), "=r"(r3) : "r"(addr));
}

#define MMA_BF16(C, a0, a1, a2, a3, b0, b1)                                   \
    asm volatile(                                                             \
        "mma.sync.aligned.m16n8k16.row.col.f32.bf16.bf16.f32 "                \
        "{%0,%1,%2,%3}, {%4,%5,%6,%7}, {%8,%9}, {%0,%1,%2,%3};"               \
        : "+f"((C)[0]), "+f"((C)[1]), "+f"((C)[2]), "+f"((C)[3])              \
        : "r"(a0), "r"(a1), "r"(a2), "r"(a3), "r"(b0), "r"(b1))

// ---------------------------------------------------------------------------
// Kernel 0: split-bf16 padded increments + counter reset.
// ---------------------------------------------------------------------------
__global__ void __launch_bounds__(256) dz_kernel(
    const float* __restrict__ X, const float* __restrict__ Y)
{
    const int gi = blockIdx.x * 256 + threadIdx.x;    // 98304 = 6144*16
    if (gi == 0) g_ctr = 0u;

    const int row = gi >> 4;
    const int d4  = gi & 15;
    const int blk = row >> 6;
    const int i   = row & 63;

    float4 v = make_float4(0.f, 0.f, 0.f, 0.f);
    if (i < MM) {
        const float* src = (blk < AP) ? (X + blk * (LL * DD))
                                      : (Y + (blk - AP) * (LL * DD));
        const float4 hi = *reinterpret_cast<const float4*>(src + (i + 1) * DD + 4 * d4);
        const float4 lo = *reinterpret_cast<const float4*>(src + i * DD + 4 * d4);
        v = make_float4(hi.x - lo.x, hi.y - lo.y, hi.z - lo.z, hi.w - lo.w);
    }

    __nv_bfloat16 h[4], l[4];
    const float vv[4] = {v.x, v.y, v.z, v.w};
#pragma unroll
    for (int c = 0; c < 4; c++) {
        h[c] = __float2bfloat16(vv[c]);
        l[c] = __float2bfloat16(vv[c] - __bfloat162float(h[c]));
    }
    __nv_bfloat162* dh = reinterpret_cast<__nv_bfloat162*>(g_dZhi) + row * 32 + 2 * d4;
    __nv_bfloat162* dl = reinterpret_cast<__nv_bfloat162*>(g_dZlo) + row * 32 + 2 * d4;
    dh[0] = __nv_bfloat162(h[0], h[1]);
    dh[1] = __nv_bfloat162(h[2], h[3]);
    dl[0] = __nv_bfloat162(l[0], l[1]);
    dl[1] = __nv_bfloat162(l[2], l[3]);
}

// ---------------------------------------------------------------------------
// Fused kernel: per 128x128 tile (u >= t):
//   phase 1: split-bf16 mma.sync SYRK with ldmatrix.x4 fragment loads
//   phase 2: epilogue to smem sub-blocks [64][66]
//   phase 3: warps 0-3 run wavefront Goursat PDE
//   phase 4: last CTA reduces
// ---------------------------------------------------------------------------
__global__ void __launch_bounds__(256, 2) sig_kernel(
    const float* __restrict__ X, const float* __restrict__ Y,
    float* __restrict__ out)
{
    extern __shared__ uint32_t smw[];
    uint32_t* sAhi = smw;
    uint32_t* sAlo = smw + TILE_U32;
    uint32_t* sBhi = smw + 2 * TILE_U32;
    uint32_t* sBlo = smw + 3 * TILE_U32;
    float*    sT   = reinterpret_cast<float*>(smw);   // pde phase alias

    const int tid  = threadIdx.x;
    const int lane = tid & 31;
    const int wid  = tid >> 5;
    const int gid  = lane >> 2;     // 0..7
    const int tig  = lane & 3;      // 0..3

    int q = blockIdx.x, t = 0;
    while (q >= NTILE - t) { q -= NTILE - t; t++; }
    const int u = t + q;
    const int gr0 = t * 128;
    const int gc0 = u * 128;

    // ---- phase 0: vectorized tile loads (uint4, coalesced) ----------------
    {
        const uint4* gh = reinterpret_cast<const uint4*>(g_dZhi);   // 8 uint4/row
        const uint4* gl = reinterpret_cast<const uint4*>(g_dZlo);
        for (int idx = tid; idx < 1024; idx += 256) {
            const int m  = idx >> 3;
            const int qq = idx & 7;
            const int ia = (gr0 + m) * 8 + qq;
            const int ib = (gc0 + m) * 8 + qq;
            reinterpret_cast<uint4*>(sAhi)[m * 9 + qq] = gh[ia];
            reinterpret_cast<uint4*>(sAlo)[m * 9 + qq] = gl[ia];
            reinterpret_cast<uint4*>(sBhi)[m * 9 + qq] = gh[ib];
            reinterpret_cast<uint4*>(sBlo)[m * 9 + qq] = gl[ib];
        }
    }
    __syncthreads();

    // ---- phase 1: mma.sync mainloop with ldmatrix fragments ---------------
    // warp wid: output rows mb..mb+15, all 128 cols.
    const int mb = wid * 16;
    float c[16][4];
#pragma unroll
    for (int j = 0; j < 16; j++)
#pragma unroll
        for (int e = 0; e < 4; e++) c[j][e] = 0.0f;

    {
        const uint32_t aHiB = smem_u32(sAhi);
        const uint32_t aLoB = smem_u32(sAlo);
        const uint32_t bHiB = smem_u32(sBhi);
        const uint32_t bLoB = smem_u32(sBlo);

        // A lane offset: quad q -> row +8 if q odd, k-col +8 bf16 if q >= 2
        const int quad = lane >> 3, lr8 = lane & 7;
        const uint32_t a_off = (uint32_t)((mb + lr8 + ((quad & 1) << 3)) * ROW_BYTES
                                          + (((quad >> 1) << 3) * 2));
        // B lane offset: lanes 0-15 -> j-pair 0, 16-31 -> j-pair 1;
        // within: lanes 0-7 k-lo, 8-15 k-hi
        const uint32_t b_off = (uint32_t)(((lane & 7) + ((lane >> 4) << 3)) * ROW_BYTES
                                          + ((((lane >> 3) & 1) << 3) * 2));

#pragma unroll
        for (int ks = 0; ks < 4; ks++) {
            uint32_t ah[4], al[4];
            ldm_x4(ah[0], ah[1], ah[2], ah[3], aHiB + a_off + 32 * ks);
            ldm_x4(al[0], al[1], al[2], al[3], aLoB + a_off + 32 * ks);

#pragma unroll
            for (int jj = 0; jj < 8; jj++) {
                uint32_t bh[4], bl[4];
                const uint32_t bo = b_off + (uint32_t)(jj * 16 * ROW_BYTES) + 32 * ks;
                ldm_x4(bh[0], bh[1], bh[2], bh[3], bHiB + bo);
                ldm_x4(bl[0], bl[1], bl[2], bl[3], bLoB + bo);

                MMA_BF16(c[2 * jj],     ah[0], ah[1], ah[2], ah[3], bh[0], bh[1]);
                MMA_BF16(c[2 * jj],     ah[0], ah[1], ah[2], ah[3], bl[0], bl[1]);
                MMA_BF16(c[2 * jj],     al[0], al[1], al[2], al[3], bh[0], bh[1]);
                MMA_BF16(c[2 * jj + 1], ah[0], ah[1], ah[2], ah[3], bh[2], bh[3]);
                MMA_BF16(c[2 * jj + 1], ah[0], ah[1], ah[2], ah[3], bl[2], bl[3]);
                MMA_BF16(c[2 * jj + 1], al[0], al[1], al[2], al[3], bh[2], bh[3]);
            }
        }
    }
    __syncthreads();   // everyone done reading A/B smem

    // ---- phase 2: epilogue to sT sub-blocks [64][TSTR] --------------------
    // D layout: c0=D[gid][2tig], c1=D[gid][2tig+1], c2=D[gid+8][2tig], c3=+1
    {
        const int subr = wid >> 2;          // row sub-block
        const int lr0  = (mb & 63) + gid;
        const int lr1  = lr0 + 8;
#pragma unroll
        for (int j = 0; j < 16; j++) {
            const int nb  = 8 * j;
            const int sub = subr * 2 + (nb >> 6);
            const int col = (nb & 63) + 2 * tig;
            float* d0 = sT + sub * SUB_FLOATS + lr0 * TSTR + col;
            float* d1 = sT + sub * SUB_FLOATS + lr1 * TSTR + col;
            *reinterpret_cast<float2*>(d0) = make_float2(c[j][0], c[j][1]);
            *reinterpret_cast<float2*>(d1) = make_float2(c[j][2], c[j][3]);
        }
    }
    __syncthreads();

    // ---- phase 3: wavefront Goursat PDE, warp sub = wid (0..3) ------------
    // K[r][c] = K[r][c-1] + K[r-1][c] + K[r-1][c-1]*(inc[r-1][c-1]-1).
    // Lane l owns cols c0=2l, c1=2l+1; 2-row block b at step s = l + b.
    if (wid < 4) {
        const int sr = wid >> 1, sc = wid & 1;
        const int pa = 2 * t + sr;
        const int pb = 2 * u + sc;
        if (pa <= pb) {
            float w;
            if (pa < AP && pb >= AP) w = -2.0f / (float)PER_GRAM;       // XY
            else w = ((pa == pb) ? 1.0f : 2.0f) / (float)PER_GRAM;      // XX/YY

            const float* base = sT + wid * SUB_FLOATS;
            const int c0  = 2 * lane;
            const int cm1 = (c0 == 0) ? 0 : (c0 - 1);
            const bool lane0 = (lane == 0);

            float t0 = 1.0f, t1 = 1.0f;
            float y0 = 1.0f;
            float nt1_prev = 1.0f;            // z-feed: prev step's nt1

#pragma unroll 1
            for (int s = 0; s < 63; s++) {
                const float ny0 = __shfl_up_sync(0xffffffffu, y0, 1);
                const float nt1 = __shfl_up_sync(0xffffffffu, t1, 1);
                const float nz  = nt1_prev;
                nt1_prev = nt1;

                const int b = s - lane;
                const bool act  = (b >= 0) & (b <= 31);
                const bool row2 = (b >= 0) & (b <= 30);

                if (act) {
                    const int r0 = 2 * b + 1;
                    const float* rp = base + (r0 - 1) * TSTR;
                    const float i00 = rp[cm1];
                    const float i01 = rp[c0];
                    const float i10 = rp[TSTR + cm1];
                    const float i11 = rp[TSTR + c0];

                    const float A = lane0 ? 1.0f : fmaf(nz, i00 - 1.0f, ny0 + t0);
                    const float B = fmaf(t0, i01 - 1.0f, A + t1);

                    if (row2) {
                        const float C = lane0 ? 1.0f : fmaf(ny0, i10 - 1.0f, nt1 + A);
                        const float D = fmaf(A, i11 - 1.0f, C + B);
                        t0 = C; t1 = D;
                    } else {
                        t0 = A; t1 = B;
                    }
                    y0 = B;
                }
            }

            if (lane == 31)
                g_Ks[blockIdx.x * 4 + wid] = w * y0;   // K[63][63], weighted
        }
    }

    // ---- phase 4: last CTA reduces ----------------------------------------
    __threadfence();
    __syncthreads();
    __shared__ bool s_is_last;
    if (tid == 0)
        s_is_last = (atomicAdd(&g_ctr, 1u) == (unsigned)(gridDim.x - 1));
    __syncthreads();
    if (!s_is_last) return;

    __shared__ float sdata[256];
    float s = 0.0f;
    for (int p = tid; p < NK2; p += 256) s += __ldcg(&g_Ks[p]);

    float s2 = 0.0f;
    for (int idx = tid; idx < AP * DD; idx += 256) {
        const int aa = idx >> 6;
        const int d  = idx & 63;
        const float diff = X[aa * (LL * DD) + d] - Y[aa * (LL * DD) + d];
        s2 = fmaf(diff, diff, s2);
    }
    s += s2 * (1.0f / (float)(AP * DD));

    sdata[tid] = s;
    __syncthreads();
    for (int k = 128; k > 0; k >>= 1) {
        if (tid < k) sdata[tid] += sdata[tid + k];
        __syncthreads();
    }
    if (tid == 0) out[0] = sdata[0];
}

// ---------------------------------------------------------------------------
extern "C" void kernel_launch(void* const* d_in, const int* in_sizes, int n_in,
                              void* d_out, int out_size)
{
    const float* X = (const float*)d_in[0];
    const float* Y = (const float*)d_in[1];
    float* out = (float*)d_out;

    static bool attr_done = false;
    if (!attr_done) {
        cudaFuncSetAttribute(sig_kernel,
                             cudaFuncAttributeMaxDynamicSharedMemorySize,
                             DYN_BYTES);
        attr_done = true;
    }

    dz_kernel<<<384, 256>>>(X, Y);
    sig_kernel<<<NTRI, 256, DYN_BYTES>>>(X, Y, out);
}